// round 9
// baseline (speedup 1.0000x reference)
#include <cuda_runtime.h>
#include <cuda_bf16.h>
#include <cstdint>

#define Hdim 64
#define Wdim 64
#define Bn   8
#define HIDc 32
#define Tn   16
#define CINx 16

using u32 = unsigned int;
using u64 = unsigned long long;

// ---------------- persistent device scratch (no allocation) ----------------
__device__ float g_c0[(size_t)Bn * HIDc * 4096];
__device__ float g_c1[(size_t)Bn * HIDc * 4096];
__device__ u32   g_xs[(size_t)Tn * Bn * CINx * 4096];       // packed (hi|lo<<16)
__device__ u32   g_h0s[2][(size_t)Bn * HIDc * 4096];        // t-parity double buffer
__device__ u32   g_h1s[2][(size_t)Bn * HIDc * 4096];
__device__ __nv_bfloat16 g_w0h[448 * 128], g_w0l[448 * 128]; // [k][n] gate-interleaved
__device__ __nv_bfloat16 g_w1h[576 * 128], g_w1l[576 * 128];

__device__ __forceinline__ float sigm(float v) {
    return __fdividef(1.0f, 1.0f + __expf(-v));
}
__device__ __forceinline__ float tanh_fast(float v) {
    return 2.0f * sigm(2.0f * v) - 1.0f;
}
__device__ __forceinline__ u32 bf16split(float v) {
    __nv_bfloat16 h = __float2bfloat16(v);
    __nv_bfloat16 lo = __float2bfloat16(v - __bfloat162float(h));
    return (u32)__bfloat16_as_ushort(h) | ((u32)__bfloat16_as_ushort(lo) << 16);
}
__device__ __forceinline__ u32 smem_u32(const void* p) {
    u32 a;
    asm("{ .reg .u64 t; cvta.to.shared.u64 t, %1; cvt.u32.u64 %0, t; }"
        : "=r"(a) : "l"(p));
    return a;
}
__device__ __forceinline__ void ldsm4t(u32* r, u32 addr) {
    asm volatile("ldmatrix.sync.aligned.m8n8.x4.trans.shared.b16 {%0,%1,%2,%3}, [%4];"
                 : "=r"(r[0]), "=r"(r[1]), "=r"(r[2]), "=r"(r[3]) : "r"(addr));
}
__device__ __forceinline__ void mma16816(float* d, const u32* a, const u32* b) {
    asm volatile(
        "mma.sync.aligned.m16n8k16.row.col.f32.bf16.bf16.f32 "
        "{%0,%1,%2,%3}, {%4,%5,%6,%7}, {%8,%9}, {%0,%1,%2,%3};"
        : "+f"(d[0]), "+f"(d[1]), "+f"(d[2]), "+f"(d[3])
        : "r"(a[0]), "r"(a[1]), "r"(a[2]), "r"(a[3]), "r"(b[0]), "r"(b[1]));
}
__device__ __forceinline__ void cp16(u32 dst, const void* src) {
    asm volatile("cp.async.cg.shared.global [%0], [%1], 16;" :: "r"(dst), "l"(src));
}
#define CP_COMMIT() asm volatile("cp.async.commit_group;" ::: "memory")
#define CP_WAIT0()  asm volatile("cp.async.wait_group 0;" ::: "memory")

// ---------------- prepass kernels ----------------
__global__ void split_x_kernel(const float* __restrict__ x)
{
    size_t i = (size_t)blockIdx.x * blockDim.x + threadIdx.x;
    const size_t N = (size_t)Tn * Bn * CINx * 4096;
    if (i < N) g_xs[i] = bf16split(x[i]);
}

template<int LAYER>
__global__ void split_w_kernel(const float* __restrict__ Wt)
{
    constexpr int KLOG = (LAYER ? (HIDc + HIDc) : (CINx + HIDc)) * 9;   // 576 / 432
    constexpr int KPAD = LAYER ? 576 : 448;
    __nv_bfloat16* wh = LAYER ? g_w1h : g_w0h;
    __nv_bfloat16* wl = LAYER ? g_w1l : g_w0l;
    int idx = blockIdx.x * blockDim.x + threadIdx.x;
    if (idx < KPAD * 128) {
        int k = idx >> 7, n = idx & 127;
        int oc = (n & 3) * HIDc + (n >> 2);      // n = hc*4 + gate
        float v = (k < KLOG) ? Wt[(size_t)oc * KLOG + k] : 0.0f;
        __nv_bfloat16 h = __float2bfloat16(v);
        wh[idx] = h;
        wl[idx] = __float2bfloat16(v - __bfloat162float(h));
    }
}

// ---------------- main step kernel ----------------
#define RSTRB 272                 // bytes per smem k-row (128 elems *2B + 16B pad)
#define TILEU (32 * 68)           // u32 per tile (32 k-rows)

template<int CIN_X, int LAYER>
__global__ __launch_bounds__(256, 2)
void step_mma(const float* __restrict__ bias,
              float* __restrict__ h_out,     // fp32 h_seq slab for this t
              int t)
{
    constexpr int CIN_TOT = CIN_X + HIDc;
    constexpr int KLOG = CIN_TOT * 9;
    constexpr int NCH  = (KLOG + 31) / 32;    // 14 / 18
    constexpr int TOT  = 3 * NCH;

    __shared__ u32 sA[2][TILEU];
    __shared__ u32 sB[2][TILEU];
    __shared__ float sb[128];

    const int tid = threadIdx.x;
    const int l = tid & 31;
    const int w = tid >> 5;
    const int b = blockIdx.y;
    const int y0 = blockIdx.x * 2;
    const int t0 = (t == 0);
    float* c_state = LAYER ? g_c1 : g_c0;
    u32* hsplit = LAYER ? g_h1s[t & 1] : g_h0s[t & 1];

    if (tid < 128) {
        const int hc = tid >> 2, g = tid & 3;
        sb[tid] = bias[g * HIDc + hc];
    }

    // warp tile: wm in {0,32,64,96}, wn in {0,64}
    const int wm = (w & 3) * 32;
    const int wn = (w >> 2) * 64;

    const u32 sAb = smem_u32(sA);
    const u32 sBb = smem_u32(sB);
    // ldmatrix lane base offsets (bytes)
    const u32 aLane = (u32)(((l & 7) + ((l >> 4) & 1) * 8) * RSTRB + ((l >> 3) & 1) * 16);
    const u32 bLane = (u32)(((l & 7) + ((l >> 3) & 1) * 8) * RSTRB + ((l >> 4) & 1) * 16);

    float acc[2][8][4];
#pragma unroll
    for (int mi = 0; mi < 2; mi++)
#pragma unroll
        for (int ni = 0; ni < 8; ni++)
#pragma unroll
            for (int q = 0; q < 4; q++) acc[mi][ni][q] = 0.0f;

    // ---------------- staging ----------------
    auto stage = [&](int p, int ch, int buf) {
        // A: im2col, 32 k-rows x 128 px. thread: k = i*4 + tid/64, px pair 2*(tid&63)
        const int px0 = (tid & 63) * 2;
        const int yrow = y0 + (px0 >> 6);
        const int xb = px0 & 63;
#pragma unroll
        for (int i = 0; i < 8; i++) {
            const int klocal = i * 4 + (tid >> 6);
            const int k = ch * 32 + klocal;
            const int ci = k / 9;
            const int rem = k - ci * 9;
            const int kyo = rem / 3 - 1;
            const int kxo = rem - (rem / 3) * 3 - 1;
            const u32* plane;
            bool pv;
            if (LAYER == 0) {
                if (ci < CIN_X) {
                    plane = g_xs + (((size_t)t * Bn + b) * CIN_X + ci) * 4096;
                    pv = true;
                } else {
                    plane = g_h0s[(t + 1) & 1] + ((size_t)b * HIDc + (ci - CIN_X)) * 4096;
                    pv = !t0;
                }
            } else {
                if (ci < HIDc) {
                    plane = g_h0s[t & 1] + ((size_t)b * HIDc + ci) * 4096;
                    pv = true;
                } else {
                    plane = g_h1s[(t + 1) & 1] + ((size_t)b * HIDc + (ci - HIDc)) * 4096;
                    pv = !t0;
                }
            }
            pv = pv && (k < KLOG);
            const int y = yrow + kyo;
            const int x1 = xb + kxo;
            u32 v1 = 0, v2 = 0;
            if (pv && y >= 0 && y < 64) {
                const u32* rowp = plane + y * 64;
                if (x1 >= 0) v1 = rowp[x1];
                if (x1 + 1 < 64) v2 = rowp[x1 + 1];
                else if (x1 + 1 == 64) v2 = 0;
                if (x1 >= 64) v1 = 0;   // cannot happen (kxo<=1, xb<=63 -> x1<=64? x1==64 impossible since xb<=63,kxo<=1 -> 64) guard:
                if (x1 == 64) v1 = 0;
            }
            const u32 h1 = (p == 1) ? (v1 >> 16) : (v1 & 0xffffu);
            const u32 h2 = (p == 1) ? (v2 >> 16) : (v2 & 0xffffu);
            sA[buf][klocal * 68 + (px0 >> 1)] = h1 | (h2 << 16);
        }
        // B: weights plane -> [k][n], cp.async 16B x2 per thread
        const __nv_bfloat16* wp = LAYER
            ? ((p == 2) ? g_w1l : g_w1h)
            : ((p == 2) ? g_w0l : g_w0h);
#pragma unroll
        for (int it = 0; it < 2; it++) {
            const int idx = tid + it * 256;
            const int row = idx >> 4;
            const int seg = idx & 15;
            cp16(sBb + (u32)(buf * TILEU + row * 68 + seg * 4) * 4u,
                 wp + (size_t)(ch * 32 + row) * 128 + seg * 8);
        }
        CP_COMMIT();
    };

    // ---------------- compute one chunk ----------------
    auto compute = [&](int buf) {
        const u32 Ab = sAb + (u32)buf * (TILEU * 4);
        const u32 Bb = sBb + (u32)buf * (TILEU * 4);
#pragma unroll
        for (int k16 = 0; k16 < 2; k16++) {
            const u32 kofs = (u32)(k16 * 16 * RSTRB);
            u32 a0[4], a1[4];
            ldsm4t(a0, Ab + kofs + aLane + (u32)(wm * 2));
            ldsm4t(a1, Ab + kofs + aLane + (u32)((wm + 16) * 2));
            u32 bb[16];
#pragma unroll
            for (int q = 0; q < 4; q++)
                ldsm4t(bb + q * 4, Bb + kofs + bLane + (u32)((wn + q * 16) * 2));
#pragma unroll
            for (int ni = 0; ni < 8; ni++) {
                const u32* bf = &bb[(ni >> 1) * 4 + (ni & 1) * 2];
                mma16816(acc[0][ni], a0, bf);
                mma16816(acc[1][ni], a1, bf);
            }
        }
    };

    // ---------------- pipelined loop over 3 passes x NCH chunks ----------------
    stage(0, 0, 0);
    for (int g = 0; g < TOT; g++) {
        CP_WAIT0();
        __syncthreads();
        const int gn = g + 1;
        if (gn < TOT) {
            const int pn = gn / NCH;
            stage(pn, gn - pn * NCH, gn & 1);
        }
        compute(g & 1);
    }

    // ---------------- epilogue: gate math via one shfl ----------------
    const int tig = l & 3;
    const int rr = l >> 2;
#pragma unroll
    for (int mi = 0; mi < 2; mi++) {
#pragma unroll
        for (int ni = 0; ni < 8; ni++) {
            float* d = acc[mi][ni];
            const float s0 = (tig & 1) ? d[0] : d[2];
            const float s1 = (tig & 1) ? d[1] : d[3];
            const float r0 = __shfl_xor_sync(0xffffffffu, s0, 1);
            const float r1 = __shfl_xor_sync(0xffffffffu, s1, 1);
            float iv, fv, ov, gv;
            int px;
            if (tig & 1) { iv = r0; fv = r1; ov = d[2]; gv = d[3]; px = wm + mi * 16 + rr + 8; }
            else         { iv = d[0]; fv = d[1]; ov = r0; gv = r1; px = wm + mi * 16 + rr; }
            const int hc = ((wn + ni * 8) >> 2) + (tig >> 1);
            iv += sb[hc * 4 + 0];
            fv += sb[hc * 4 + 1];
            ov += sb[hc * 4 + 2];
            gv += sb[hc * 4 + 3];
            const int yy = y0 + (px >> 6);
            const int xx = px & 63;
            const size_t off = (((size_t)b * HIDc + hc) * Hdim + yy) * Wdim + xx;
            const float cp = t0 ? 0.0f : c_state[off];
            const float cn = sigm(fv) * cp + sigm(iv) * tanh_fast(gv);
            const float hn = sigm(ov) * tanh_fast(cn);
            c_state[off] = cn;
            h_out[off] = hn;
            hsplit[off] = bf16split(hn);
        }
    }
}

// Writes the four tail regions: h0_T, c0_T, h1_T, c1_T.
__global__ void tail_copy(float* __restrict__ out)
{
    const size_t NP = (size_t)Bn * HIDc * 4096;
    size_t i4 = (size_t)blockIdx.x * blockDim.x + threadIdx.x;
    const size_t N4 = NP / 4;
    if (i4 < N4) {
        const size_t SEQ = Tn * NP;
        float4* o4 = (float4*)out;
        const float4* c0 = (const float4*)g_c0;
        const float4* c1 = (const float4*)g_c1;
        const size_t base = (2 * SEQ) / 4;
        o4[base + 0 * N4 + i4] = o4[((Tn - 1) * NP) / 4 + i4];
        o4[base + 1 * N4 + i4] = c0[i4];
        o4[base + 2 * N4 + i4] = o4[(SEQ + (Tn - 1) * NP) / 4 + i4];
        o4[base + 3 * N4 + i4] = c1[i4];
    }
}

extern "C" void kernel_launch(void* const* d_in, const int* in_sizes, int n_in,
                              void* d_out, int out_size)
{
    const float* x  = (const float*)d_in[0];
    const float* W0 = (const float*)d_in[1];
    const float* b0 = (const float*)d_in[2];
    const float* W1 = (const float*)d_in[3];
    const float* b1 = (const float*)d_in[4];
    float* out = (float*)d_out;

    const size_t HS = (size_t)Bn * HIDc * 4096;
    float* hseq0 = out;
    float* hseq1 = out + (size_t)Tn * HS;

    // prepasses (deterministic each replay)
    {
        const size_t NX = (size_t)Tn * Bn * CINx * 4096;
        split_x_kernel<<<(unsigned)((NX + 255) / 256), 256>>>(x);
        split_w_kernel<0><<<(448 * 128 + 255) / 256, 256>>>(W0);
        split_w_kernel<1><<<(576 * 128 + 255) / 256, 256>>>(W1);
    }

    dim3 grid(32, Bn);
    for (int t = 0; t < Tn; t++) {
        step_mma<CINx, 0><<<grid, 256>>>(b0, hseq0 + (size_t)t * HS, t);
        step_mma<HIDc, 1><<<grid, 256>>>(b1, hseq1 + (size_t)t * HS, t);
    }
    tail_copy<<<(unsigned)((HS / 4 + 255) / 256), 256>>>(out);
}

// round 10
// speedup vs baseline: 1.8325x; 1.8325x over previous
#include <cuda_runtime.h>
#include <cuda_bf16.h>
#include <cstdint>

#define Hdim 64
#define Wdim 64
#define Bn   8
#define HIDc 32
#define Tn   16
#define CINx 16

using u32 = unsigned int;
using u64 = unsigned long long;

// ---------------- persistent device scratch (no allocation) ----------------
__device__ float g_c0[(size_t)Bn * HIDc * 4096];
__device__ float g_c1[(size_t)Bn * HIDc * 4096];
__device__ u32   g_xs[(size_t)Tn * Bn * CINx * 4096];       // packed (hi|lo<<16)
__device__ u32   g_h0s[2][(size_t)Bn * HIDc * 4096];        // t-parity double buffer
__device__ u32   g_h1s[2][(size_t)Bn * HIDc * 4096];
__device__ __nv_bfloat16 g_w0h[448 * 128], g_w0l[448 * 128]; // [k][n] gate-interleaved
__device__ __nv_bfloat16 g_w1h[576 * 128], g_w1l[576 * 128];

__device__ __forceinline__ float sigm(float v) {
    return __fdividef(1.0f, 1.0f + __expf(-v));
}
__device__ __forceinline__ float tanh_fast(float v) {
    return 2.0f * sigm(2.0f * v) - 1.0f;
}
__device__ __forceinline__ u32 bf16split(float v) {
    __nv_bfloat16 h = __float2bfloat16(v);
    __nv_bfloat16 lo = __float2bfloat16(v - __bfloat162float(h));
    return (u32)__bfloat16_as_ushort(h) | ((u32)__bfloat16_as_ushort(lo) << 16);
}
__device__ __forceinline__ u32 smem_u32(const void* p) {
    u32 a;
    asm("{ .reg .u64 t; cvta.to.shared.u64 t, %1; cvt.u32.u64 %0, t; }"
        : "=r"(a) : "l"(p));
    return a;
}
__device__ __forceinline__ void ldsm4t(u32* r, u32 addr) {
    asm volatile("ldmatrix.sync.aligned.m8n8.x4.trans.shared.b16 {%0,%1,%2,%3}, [%4];"
                 : "=r"(r[0]), "=r"(r[1]), "=r"(r[2]), "=r"(r[3]) : "r"(addr));
}
__device__ __forceinline__ void mma16816(float* d, const u32* a, const u32* b) {
    asm volatile(
        "mma.sync.aligned.m16n8k16.row.col.f32.bf16.bf16.f32 "
        "{%0,%1,%2,%3}, {%4,%5,%6,%7}, {%8,%9}, {%0,%1,%2,%3};"
        : "+f"(d[0]), "+f"(d[1]), "+f"(d[2]), "+f"(d[3])
        : "r"(a[0]), "r"(a[1]), "r"(a[2]), "r"(a[3]), "r"(b[0]), "r"(b[1]));
}
__device__ __forceinline__ void cp16(u32 dst, const void* src) {
    asm volatile("cp.async.cg.shared.global [%0], [%1], 16;" :: "r"(dst), "l"(src));
}
#define CP_COMMIT() asm volatile("cp.async.commit_group;" ::: "memory")
#define CP_WAIT0()  asm volatile("cp.async.wait_group 0;" ::: "memory")

// ---------------- prepass kernels ----------------
__global__ void split_x_kernel(const float* __restrict__ x)
{
    size_t i = (size_t)blockIdx.x * blockDim.x + threadIdx.x;
    const size_t N = (size_t)Tn * Bn * CINx * 4096;
    if (i < N) g_xs[i] = bf16split(x[i]);
}

template<int LAYER>
__global__ void split_w_kernel(const float* __restrict__ Wt)
{
    constexpr int KLOG = (LAYER ? (HIDc + HIDc) : (CINx + HIDc)) * 9;   // 576 / 432
    constexpr int KPAD = LAYER ? 576 : 448;
    __nv_bfloat16* wh = LAYER ? g_w1h : g_w0h;
    __nv_bfloat16* wl = LAYER ? g_w1l : g_w0l;
    int idx = blockIdx.x * blockDim.x + threadIdx.x;
    if (idx < KPAD * 128) {
        int k = idx >> 7, n = idx & 127;
        int oc = (n & 3) * HIDc + (n >> 2);      // n = hc*4 + gate
        float v = (k < KLOG) ? Wt[(size_t)oc * KLOG + k] : 0.0f;
        __nv_bfloat16 h = __float2bfloat16(v);
        wh[idx] = h;
        wl[idx] = __float2bfloat16(v - __bfloat162float(h));
    }
}

// ---------------- main step kernel ----------------
#define RSTRB 272                 // bytes per smem k-row (128 elems *2B + 16B pad)
#define TILEU (32 * 68)           // u32 per tile (32 k-rows)
#define SMEM_DYN (2 * 4 * TILEU * 4)   // 2 buffers x 4 tiles = 69632 B

// Tile order within a buffer: [0]=A_hi [1]=A_lo [2]=B_hi [3]=B_lo
template<int CIN_X, int LAYER>
__global__ __launch_bounds__(256, 2)
void step_mma(const float* __restrict__ bias,
              float* __restrict__ h_out,     // fp32 h_seq slab for this t
              int t)
{
    constexpr int CIN_TOT = CIN_X + HIDc;
    constexpr int KLOG = CIN_TOT * 9;
    constexpr int NCH  = (KLOG + 31) / 32;    // 14 / 18

    extern __shared__ u32 dsm[];
    __shared__ float sb[128];

    const int tid = threadIdx.x;
    const int l = tid & 31;
    const int w = tid >> 5;
    const int b = blockIdx.y;
    const int y0 = blockIdx.x * 2;
    const int t0 = (t == 0);
    float* c_state = LAYER ? g_c1 : g_c0;
    u32* hsplit = LAYER ? g_h1s[t & 1] : g_h0s[t & 1];

    if (tid < 128) {
        const int hc = tid >> 2, g = tid & 3;
        sb[tid] = bias[g * HIDc + hc];
    }

    // warp tile: wm in {0,32,64,96}, wn in {0,64}
    const int wm = (w & 3) * 32;
    const int wn = (w >> 2) * 64;

    const u32 smb = smem_u32(dsm);
    // ldmatrix lane base offsets (bytes) — identical to R9 (validated)
    const u32 aLane = (u32)(((l & 7) + ((l >> 4) & 1) * 8) * RSTRB + ((l >> 3) & 1) * 16);
    const u32 bLane = (u32)(((l & 7) + ((l >> 3) & 1) * 8) * RSTRB + ((l >> 4) & 1) * 16);

    float acc[2][8][4];
#pragma unroll
    for (int mi = 0; mi < 2; mi++)
#pragma unroll
        for (int ni = 0; ni < 8; ni++)
#pragma unroll
            for (int q = 0; q < 4; q++) acc[mi][ni][q] = 0.0f;

    // ---------------- staging: ONE pass per chunk, all 4 tiles ----------------
    auto stage = [&](int ch, int buf) {
        u32* Ah = dsm + (buf * 4 + 0) * TILEU;
        u32* Al = dsm + (buf * 4 + 1) * TILEU;
        // A: im2col, 32 k-rows x 128 px. thread: k = i*4 + tid/64, px pair 2*(tid&63)
        const int px0 = (tid & 63) * 2;
        const int yrow = y0 + (px0 >> 6);
        const int xb = px0 & 63;
#pragma unroll
        for (int i = 0; i < 8; i++) {
            const int klocal = i * 4 + (tid >> 6);
            const int k = ch * 32 + klocal;
            const int ci = k / 9;
            const int rem = k - ci * 9;
            const int kyo = rem / 3 - 1;
            const int kxo = rem - (rem / 3) * 3 - 1;
            const u32* plane;
            bool pv;
            if (LAYER == 0) {
                if (ci < CIN_X) {
                    plane = g_xs + (((size_t)t * Bn + b) * CIN_X + ci) * 4096;
                    pv = true;
                } else {
                    plane = g_h0s[(t + 1) & 1] + ((size_t)b * HIDc + (ci - CIN_X)) * 4096;
                    pv = !t0;
                }
            } else {
                if (ci < HIDc) {
                    plane = g_h0s[t & 1] + ((size_t)b * HIDc + ci) * 4096;
                    pv = true;
                } else {
                    plane = g_h1s[(t + 1) & 1] + ((size_t)b * HIDc + (ci - HIDc)) * 4096;
                    pv = !t0;
                }
            }
            pv = pv && (k < KLOG);
            const int y = yrow + kyo;
            const int x1 = xb + kxo;
            u32 v1 = 0, v2 = 0;
            if (pv && y >= 0 && y < 64) {
                const u32* rowp = plane + y * 64;
                if (x1 >= 0 && x1 < 64) v1 = rowp[x1];
                if (x1 + 1 >= 0 && x1 + 1 < 64) v2 = rowp[x1 + 1];
            }
            const int si = klocal * 68 + (px0 >> 1);
            Ah[si] = (v1 & 0xffffu) | (v2 << 16);            // hi halves
            Al[si] = (v1 >> 16) | (v2 & 0xffff0000u);        // lo halves
        }
        // B: both planes via cp.async; 32 rows x 16 segs per tile
        const __nv_bfloat16* wph = LAYER ? g_w1h : g_w0h;
        const __nv_bfloat16* wpl = LAYER ? g_w1l : g_w0l;
        const u32 Bh = smb + (u32)((buf * 4 + 2) * TILEU) * 4u;
        const u32 Bl = smb + (u32)((buf * 4 + 3) * TILEU) * 4u;
#pragma unroll
        for (int it = 0; it < 2; it++) {
            const int idx = tid + it * 256;
            const int row = idx >> 4;
            const int seg = idx & 15;
            const u32 dof = (u32)(row * 68 + seg * 4) * 4u;
            const size_t sof = (size_t)(ch * 32 + row) * 128 + seg * 8;
            cp16(Bh + dof, wph + sof);
            cp16(Bl + dof, wpl + sof);
        }
        CP_COMMIT();
    };

    // ---------------- compute: 3 split sub-passes on one staged chunk ----------------
    auto compute = [&](int buf) {
#pragma unroll
        for (int sp = 0; sp < 3; sp++) {
            const int aSel = (sp == 1) ? 1 : 0;          // al only in pass 1
            const int bSel = (sp == 2) ? 3 : 2;          // bl only in pass 2
            const u32 Ab = smb + (u32)((buf * 4 + aSel) * TILEU) * 4u;
            const u32 Bb = smb + (u32)((buf * 4 + bSel) * TILEU) * 4u;
#pragma unroll
            for (int k16 = 0; k16 < 2; k16++) {
                const u32 kofs = (u32)(k16 * 16 * RSTRB);
                u32 a0[4], a1[4];
                ldsm4t(a0, Ab + kofs + aLane + (u32)(wm * 2));
                ldsm4t(a1, Ab + kofs + aLane + (u32)((wm + 16) * 2));
                u32 bb[16];
#pragma unroll
                for (int q = 0; q < 4; q++)
                    ldsm4t(bb + q * 4, Bb + kofs + bLane + (u32)((wn + q * 16) * 2));
#pragma unroll
                for (int ni = 0; ni < 8; ni++) {
                    const u32* bf = &bb[(ni >> 1) * 4 + (ni & 1) * 2];
                    mma16816(acc[0][ni], a0, bf);
                    mma16816(acc[1][ni], a1, bf);
                }
            }
        }
    };

    // ---------------- pipelined chunk loop ----------------
    stage(0, 0);
    for (int c = 0; c < NCH; c++) {
        CP_WAIT0();
        __syncthreads();
        if (c + 1 < NCH) stage(c + 1, (c + 1) & 1);
        compute(c & 1);
    }

    // ---------------- epilogue: gate math via one shfl (identical to R9) ----------------
    const int tig = l & 3;
    const int rr = l >> 2;
#pragma unroll
    for (int mi = 0; mi < 2; mi++) {
#pragma unroll
        for (int ni = 0; ni < 8; ni++) {
            float* d = acc[mi][ni];
            const float s0 = (tig & 1) ? d[0] : d[2];
            const float s1 = (tig & 1) ? d[1] : d[3];
            const float r0 = __shfl_xor_sync(0xffffffffu, s0, 1);
            const float r1 = __shfl_xor_sync(0xffffffffu, s1, 1);
            float iv, fv, ov, gv;
            int px;
            if (tig & 1) { iv = r0; fv = r1; ov = d[2]; gv = d[3]; px = wm + mi * 16 + rr + 8; }
            else         { iv = d[0]; fv = d[1]; ov = r0; gv = r1; px = wm + mi * 16 + rr; }
            const int hc = ((wn + ni * 8) >> 2) + (tig >> 1);
            iv += sb[hc * 4 + 0];
            fv += sb[hc * 4 + 1];
            ov += sb[hc * 4 + 2];
            gv += sb[hc * 4 + 3];
            const int yy = y0 + (px >> 6);
            const int xx = px & 63;
            const size_t off = (((size_t)b * HIDc + hc) * Hdim + yy) * Wdim + xx;
            const float cp = t0 ? 0.0f : c_state[off];
            const float cn = sigm(fv) * cp + sigm(iv) * tanh_fast(gv);
            const float hn = sigm(ov) * tanh_fast(cn);
            c_state[off] = cn;
            h_out[off] = hn;
            hsplit[off] = bf16split(hn);
        }
    }
}

// Writes the four tail regions: h0_T, c0_T, h1_T, c1_T.
__global__ void tail_copy(float* __restrict__ out)
{
    const size_t NP = (size_t)Bn * HIDc * 4096;
    size_t i4 = (size_t)blockIdx.x * blockDim.x + threadIdx.x;
    const size_t N4 = NP / 4;
    if (i4 < N4) {
        const size_t SEQ = Tn * NP;
        float4* o4 = (float4*)out;
        const float4* c0 = (const float4*)g_c0;
        const float4* c1 = (const float4*)g_c1;
        const size_t base = (2 * SEQ) / 4;
        o4[base + 0 * N4 + i4] = o4[((Tn - 1) * NP) / 4 + i4];
        o4[base + 1 * N4 + i4] = c0[i4];
        o4[base + 2 * N4 + i4] = o4[(SEQ + (Tn - 1) * NP) / 4 + i4];
        o4[base + 3 * N4 + i4] = c1[i4];
    }
}

extern "C" void kernel_launch(void* const* d_in, const int* in_sizes, int n_in,
                              void* d_out, int out_size)
{
    const float* x  = (const float*)d_in[0];
    const float* W0 = (const float*)d_in[1];
    const float* b0 = (const float*)d_in[2];
    const float* W1 = (const float*)d_in[3];
    const float* b1 = (const float*)d_in[4];
    float* out = (float*)d_out;

    cudaFuncSetAttribute(step_mma<CINx, 0>,
                         cudaFuncAttributeMaxDynamicSharedMemorySize, SMEM_DYN);
    cudaFuncSetAttribute(step_mma<HIDc, 1>,
                         cudaFuncAttributeMaxDynamicSharedMemorySize, SMEM_DYN);

    const size_t HS = (size_t)Bn * HIDc * 4096;
    float* hseq0 = out;
    float* hseq1 = out + (size_t)Tn * HS;

    // prepasses (deterministic each replay)
    {
        const size_t NX = (size_t)Tn * Bn * CINx * 4096;
        split_x_kernel<<<(unsigned)((NX + 255) / 256), 256>>>(x);
        split_w_kernel<0><<<(448 * 128 + 255) / 256, 256>>>(W0);
        split_w_kernel<1><<<(576 * 128 + 255) / 256, 256>>>(W1);
    }

    dim3 grid(32, Bn);
    for (int t = 0; t < Tn; t++) {
        step_mma<CINx, 0><<<grid, 256, SMEM_DYN>>>(b0, hseq0 + (size_t)t * HS, t);
        step_mma<HIDc, 1><<<grid, 256, SMEM_DYN>>>(b1, hseq1 + (size_t)t * HS, t);
    }
    tail_copy<<<(unsigned)((HS / 4 + 255) / 256), 256>>>(out);
}

// round 11
// speedup vs baseline: 1.8687x; 1.0198x over previous
#include <cuda_runtime.h>
#include <cuda_bf16.h>
#include <cstdint>

#define Hdim 64
#define Wdim 64
#define Bn   8
#define HIDc 32
#define Tn   16
#define CINx 16

#define PLANE 4224        // 66 rows x 64 bf16 per shifted plane

using u32 = unsigned int;
using u64 = unsigned long long;

// ---------------- persistent device scratch (no allocation) ----------------
__device__ float g_c0[(size_t)Bn * HIDc * 4096];
__device__ float g_c1[(size_t)Bn * HIDc * 4096];
// x input: [T*B*CIN][3 shifts][66][64] bf16, hi and lo planes.
__device__ __align__(128) __nv_bfloat16 g_xph[(size_t)Tn * Bn * CINx * 3 * PLANE];
__device__ __align__(128) __nv_bfloat16 g_xpl[(size_t)Tn * Bn * CINx * 3 * PLANE];
// hidden states: [parity][B*HID][3][66][64]
__device__ __align__(128) __nv_bfloat16 g_h0ph[2][(size_t)Bn * HIDc * 3 * PLANE];
__device__ __align__(128) __nv_bfloat16 g_h0pl[2][(size_t)Bn * HIDc * 3 * PLANE];
__device__ __align__(128) __nv_bfloat16 g_h1ph[2][(size_t)Bn * HIDc * 3 * PLANE];
__device__ __align__(128) __nv_bfloat16 g_h1pl[2][(size_t)Bn * HIDc * 3 * PLANE];
// weights [k][n] gate-interleaved, hi/lo
__device__ __align__(128) __nv_bfloat16 g_w0h[448 * 128], g_w0l[448 * 128];
__device__ __align__(128) __nv_bfloat16 g_w1h[576 * 128], g_w1l[576 * 128];

__device__ __forceinline__ float sigm(float v) {
    return __fdividef(1.0f, 1.0f + __expf(-v));
}
__device__ __forceinline__ float tanh_fast(float v) {
    return 2.0f * sigm(2.0f * v) - 1.0f;
}
__device__ __forceinline__ u32 smem_u32(const void* p) {
    u32 a;
    asm("{ .reg .u64 t; cvta.to.shared.u64 t, %1; cvt.u32.u64 %0, t; }"
        : "=r"(a) : "l"(p));
    return a;
}
__device__ __forceinline__ void ldsm4t(u32* r, u32 addr) {
    asm volatile("ldmatrix.sync.aligned.m8n8.x4.trans.shared.b16 {%0,%1,%2,%3}, [%4];"
                 : "=r"(r[0]), "=r"(r[1]), "=r"(r[2]), "=r"(r[3]) : "r"(addr));
}
__device__ __forceinline__ void mma16816(float* d, const u32* a, const u32* b) {
    asm volatile(
        "mma.sync.aligned.m16n8k16.row.col.f32.bf16.bf16.f32 "
        "{%0,%1,%2,%3}, {%4,%5,%6,%7}, {%8,%9}, {%0,%1,%2,%3};"
        : "+f"(d[0]), "+f"(d[1]), "+f"(d[2]), "+f"(d[3])
        : "r"(a[0]), "r"(a[1]), "r"(a[2]), "r"(a[3]), "r"(b[0]), "r"(b[1]));
}
__device__ __forceinline__ void cp16(u32 dst, const void* src) {
    asm volatile("cp.async.cg.shared.global [%0], [%1], 16;" :: "r"(dst), "l"(src));
}
#define CP_COMMIT() asm volatile("cp.async.commit_group;" ::: "memory")
#define CP_WAIT0()  asm volatile("cp.async.wait_group 0;" ::: "memory")

// ---------------- prepass kernels ----------------
// Build x shifted planes: plane[s] row (y+1) col c holds x[y][c+s-1] (0 OOB).
// Equivalently x value at (y,xx) lands at col c = xx+1-s of plane s.
__global__ void build_x_planes(const float* __restrict__ x)
{
    size_t i = (size_t)blockIdx.x * blockDim.x + threadIdx.x;
    const size_t N = (size_t)Tn * Bn * CINx * 4096;
    if (i >= N) return;
    const size_t pi = i >> 12;           // (t*B+b)*CIN+ci
    const int px = (int)(i & 4095);
    const int y = px >> 6, xx = px & 63;
    const float v = x[i];
    const __nv_bfloat16 hh = __float2bfloat16(v);
    const __nv_bfloat16 hl = __float2bfloat16(v - __bfloat162float(hh));
    const size_t base = pi * 3 * PLANE + (size_t)(y + 1) * 64;
#pragma unroll
    for (int s = 0; s < 3; s++) {
        const int c = xx + 1 - s;
        if (c >= 0 && c < 64) {
            g_xph[base + (size_t)s * PLANE + c] = hh;
            g_xpl[base + (size_t)s * PLANE + c] = hl;
        }
    }
}

template<int LAYER>
__global__ void split_w_kernel(const float* __restrict__ Wt)
{
    constexpr int KLOG = (LAYER ? (HIDc + HIDc) : (CINx + HIDc)) * 9;   // 576 / 432
    constexpr int KPAD = LAYER ? 576 : 448;
    __nv_bfloat16* wh = LAYER ? g_w1h : g_w0h;
    __nv_bfloat16* wl = LAYER ? g_w1l : g_w0l;
    int idx = blockIdx.x * blockDim.x + threadIdx.x;
    if (idx < KPAD * 128) {
        int k = idx >> 7, n = idx & 127;
        int oc = (n & 3) * HIDc + (n >> 2);      // n = hc*4 + gate
        float v = (k < KLOG) ? Wt[(size_t)oc * KLOG + k] : 0.0f;
        __nv_bfloat16 h = __float2bfloat16(v);
        wh[idx] = h;
        wl[idx] = __float2bfloat16(v - __bfloat162float(h));
    }
}

// ---------------- main step kernel ----------------
#define RSTRB 272                 // bytes per smem k-row (128 elems *2B + 16B pad)
#define TILEU (32 * 68)           // u32 per tile (32 k-rows)
#define SMEM_DYN (2 * 4 * TILEU * 4)   // 2 buffers x 4 tiles = 69632 B

// Tile order within a buffer: [0]=A_hi [1]=A_lo [2]=B_hi [3]=B_lo
template<int CIN_X, int LAYER>
__global__ __launch_bounds__(256, 2)
void step_mma(const float* __restrict__ bias,
              float* __restrict__ h_out,     // fp32 h_seq slab for this t
              int t)
{
    constexpr int CIN_TOT = CIN_X + HIDc;
    constexpr int KLOG = CIN_TOT * 9;
    constexpr int NCH  = (KLOG + 31) / 32;    // 14 / 18

    extern __shared__ __align__(128) u32 dsm[];
    __shared__ float sb[128];

    const int tid = threadIdx.x;
    const int l = tid & 31;
    const int w = tid >> 5;
    const int b = blockIdx.y;
    const int y0 = blockIdx.x * 2;
    const int t0 = (t == 0);
    float* c_state = LAYER ? g_c1 : g_c0;
    __nv_bfloat16* hph = LAYER ? g_h1ph[t & 1] : g_h0ph[t & 1];
    __nv_bfloat16* hpl = LAYER ? g_h1pl[t & 1] : g_h0pl[t & 1];

    if (tid < 128) {
        const int hc = tid >> 2, g = tid & 3;
        sb[tid] = bias[g * HIDc + hc];
    }

    // warp tile: wm in {0,32,64,96}, wn in {0,64}
    const int wm = (w & 3) * 32;
    const int wn = (w >> 2) * 64;

    const u32 smb = smem_u32(dsm);
    // ldmatrix lane base offsets (bytes) — validated in R9/R10
    const u32 aLane = (u32)(((l & 7) + ((l >> 4) & 1) * 8) * RSTRB + ((l >> 3) & 1) * 16);
    const u32 bLane = (u32)(((l & 7) + ((l >> 3) & 1) * 8) * RSTRB + ((l >> 4) & 1) * 16);

    float acc[2][8][4];
#pragma unroll
    for (int mi = 0; mi < 2; mi++)
#pragma unroll
        for (int ni = 0; ni < 8; ni++)
#pragma unroll
            for (int q = 0; q < 4; q++) acc[mi][ni][q] = 0.0f;

    // ---------------- staging: pure cp.async, 8 x 16B per thread ----------------
    auto stage = [&](int ch, int buf) {
        // A: thread group of 8 per k-row; thread does 4 of the 32 cp16s.
        const int kr  = tid >> 3;            // 0..31
        const int sub = tid & 7;             // 0..7
        const int k = ch * 32 + kr;
        int ci = k / 9;
        const int rem = k - ci * 9;
        const int ky = rem / 3;              // 0..2 (offset = ky-1)
        int s = rem - ky * 3;                // kx+1
        bool zero = (k >= KLOG);
        if (zero) { ci = 0; s = 0; }
        const __nv_bfloat16 *ph, *pl;
        if (LAYER == 0) {
            if (ci < CIN_X) {
                const size_t pi = ((size_t)((t * Bn + b) * CINx + ci) * 3 + s) * PLANE;
                ph = g_xph + pi; pl = g_xpl + pi;
            } else {
                if (t0) zero = true;
                const size_t pi = ((size_t)(b * HIDc + (ci - CIN_X)) * 3 + s) * PLANE;
                ph = g_h0ph[(t + 1) & 1] + pi; pl = g_h0pl[(t + 1) & 1] + pi;
            }
        } else {
            if (ci < HIDc) {
                const size_t pi = ((size_t)(b * HIDc + ci) * 3 + s) * PLANE;
                ph = g_h0ph[t & 1] + pi; pl = g_h0pl[t & 1] + pi;
            } else {
                if (t0) zero = true;
                const size_t pi = ((size_t)(b * HIDc + (ci - HIDc)) * 3 + s) * PLANE;
                ph = g_h1ph[(t + 1) & 1] + pi; pl = g_h1pl[(t + 1) & 1] + pi;
            }
        }
#pragma unroll
        for (int j = 0; j < 4; j++) {
            const int op = sub * 4 + j;      // 0..31
            const int tsel = op >> 4;        // 0 = hi tile, 1 = lo tile
            const int seg = op & 15;         // 16B segment within k-row
            const int prow = zero ? 0 : (y0 + ky + (seg >> 3));  // plane row
            const __nv_bfloat16* src = (tsel ? pl : ph) + prow * 64 + (seg & 7) * 8;
            const u32 dst = smb + (u32)(((buf * 4 + tsel) * TILEU + kr * 68) * 4)
                                + (u32)(seg * 16);
            cp16(dst, src);
        }
        // B: both planes; 32 rows x 16 segs per tile
        const __nv_bfloat16* wph = LAYER ? g_w1h : g_w0h;
        const __nv_bfloat16* wpl = LAYER ? g_w1l : g_w0l;
        const u32 Bh = smb + (u32)((buf * 4 + 2) * TILEU) * 4u;
        const u32 Bl = smb + (u32)((buf * 4 + 3) * TILEU) * 4u;
#pragma unroll
        for (int it = 0; it < 2; it++) {
            const int idx = tid + it * 256;
            const int row = idx >> 4;
            const int seg = idx & 15;
            const u32 dof = (u32)(row * 68 + seg * 4) * 4u;
            const size_t sof = (size_t)(ch * 32 + row) * 128 + seg * 8;
            cp16(Bh + dof, wph + sof);
            cp16(Bl + dof, wpl + sof);
        }
        CP_COMMIT();
    };

    // ---------------- compute: 3 split sub-passes on one staged chunk ----------------
    auto compute = [&](int buf) {
#pragma unroll
        for (int sp = 0; sp < 3; sp++) {
            const int aSel = (sp == 1) ? 1 : 0;          // al only in pass 1
            const int bSel = (sp == 2) ? 3 : 2;          // bl only in pass 2
            const u32 Ab = smb + (u32)((buf * 4 + aSel) * TILEU) * 4u;
            const u32 Bb = smb + (u32)((buf * 4 + bSel) * TILEU) * 4u;
#pragma unroll
            for (int k16 = 0; k16 < 2; k16++) {
                const u32 kofs = (u32)(k16 * 16 * RSTRB);
                u32 a0[4], a1[4];
                ldsm4t(a0, Ab + kofs + aLane + (u32)(wm * 2));
                ldsm4t(a1, Ab + kofs + aLane + (u32)((wm + 16) * 2));
                u32 bb[16];
#pragma unroll
                for (int q = 0; q < 4; q++)
                    ldsm4t(bb + q * 4, Bb + kofs + bLane + (u32)((wn + q * 16) * 2));
#pragma unroll
                for (int ni = 0; ni < 8; ni++) {
                    const u32* bf = &bb[(ni >> 1) * 4 + (ni & 1) * 2];
                    mma16816(acc[0][ni], a0, bf);
                    mma16816(acc[1][ni], a1, bf);
                }
            }
        }
    };

    // ---------------- pipelined chunk loop ----------------
    stage(0, 0);
    for (int c = 0; c < NCH; c++) {
        CP_WAIT0();
        __syncthreads();
        if (c + 1 < NCH) stage(c + 1, (c + 1) & 1);
        compute(c & 1);
    }

    // ---------------- epilogue: gate math + h plane writes ----------------
    const int tig = l & 3;
    const int rr = l >> 2;
#pragma unroll
    for (int mi = 0; mi < 2; mi++) {
#pragma unroll
        for (int ni = 0; ni < 8; ni++) {
            float* d = acc[mi][ni];
            const float s0 = (tig & 1) ? d[0] : d[2];
            const float s1 = (tig & 1) ? d[1] : d[3];
            const float r0 = __shfl_xor_sync(0xffffffffu, s0, 1);
            const float r1 = __shfl_xor_sync(0xffffffffu, s1, 1);
            float iv, fv, ov, gv;
            int px;
            if (tig & 1) { iv = r0; fv = r1; ov = d[2]; gv = d[3]; px = wm + mi * 16 + rr + 8; }
            else         { iv = d[0]; fv = d[1]; ov = r0; gv = r1; px = wm + mi * 16 + rr; }
            const int hc = ((wn + ni * 8) >> 2) + (tig >> 1);
            iv += sb[hc * 4 + 0];
            fv += sb[hc * 4 + 1];
            ov += sb[hc * 4 + 2];
            gv += sb[hc * 4 + 3];
            const int yy = y0 + (px >> 6);
            const int xx = px & 63;
            const size_t off = (((size_t)b * HIDc + hc) * Hdim + yy) * Wdim + xx;
            const float cp = t0 ? 0.0f : c_state[off];
            const float cn = sigm(fv) * cp + sigm(iv) * tanh_fast(gv);
            const float hn = sigm(ov) * tanh_fast(cn);
            c_state[off] = cn;
            h_out[off] = hn;
            const __nv_bfloat16 hh = __float2bfloat16(hn);
            const __nv_bfloat16 hl = __float2bfloat16(hn - __bfloat162float(hh));
            const size_t pb = (size_t)(b * HIDc + hc) * 3 * PLANE + (size_t)(yy + 1) * 64;
#pragma unroll
            for (int s2 = 0; s2 < 3; s2++) {
                const int cc = xx + 1 - s2;
                if (cc >= 0 && cc < 64) {
                    hph[pb + (size_t)s2 * PLANE + cc] = hh;
                    hpl[pb + (size_t)s2 * PLANE + cc] = hl;
                }
            }
        }
    }
}

// Writes the four tail regions: h0_T, c0_T, h1_T, c1_T.
__global__ void tail_copy(float* __restrict__ out)
{
    const size_t NP = (size_t)Bn * HIDc * 4096;
    size_t i4 = (size_t)blockIdx.x * blockDim.x + threadIdx.x;
    const size_t N4 = NP / 4;
    if (i4 < N4) {
        const size_t SEQ = Tn * NP;
        float4* o4 = (float4*)out;
        const float4* c0 = (const float4*)g_c0;
        const float4* c1 = (const float4*)g_c1;
        const size_t base = (2 * SEQ) / 4;
        o4[base + 0 * N4 + i4] = o4[((Tn - 1) * NP) / 4 + i4];
        o4[base + 1 * N4 + i4] = c0[i4];
        o4[base + 2 * N4 + i4] = o4[(SEQ + (Tn - 1) * NP) / 4 + i4];
        o4[base + 3 * N4 + i4] = c1[i4];
    }
}

extern "C" void kernel_launch(void* const* d_in, const int* in_sizes, int n_in,
                              void* d_out, int out_size)
{
    const float* x  = (const float*)d_in[0];
    const float* W0 = (const float*)d_in[1];
    const float* b0 = (const float*)d_in[2];
    const float* W1 = (const float*)d_in[3];
    const float* b1 = (const float*)d_in[4];
    float* out = (float*)d_out;

    cudaFuncSetAttribute(step_mma<CINx, 0>,
                         cudaFuncAttributeMaxDynamicSharedMemorySize, SMEM_DYN);
    cudaFuncSetAttribute(step_mma<HIDc, 1>,
                         cudaFuncAttributeMaxDynamicSharedMemorySize, SMEM_DYN);

    const size_t HS = (size_t)Bn * HIDc * 4096;
    float* hseq0 = out;
    float* hseq1 = out + (size_t)Tn * HS;

    // prepasses (deterministic each replay)
    {
        const size_t NX = (size_t)Tn * Bn * CINx * 4096;
        build_x_planes<<<(unsigned)((NX + 255) / 256), 256>>>(x);
        split_w_kernel<0><<<(448 * 128 + 255) / 256, 256>>>(W0);
        split_w_kernel<1><<<(576 * 128 + 255) / 256, 256>>>(W1);
    }

    dim3 grid(32, Bn);
    for (int t = 0; t < Tn; t++) {
        step_mma<CINx, 0><<<grid, 256, SMEM_DYN>>>(b0, hseq0 + (size_t)t * HS, t);
        step_mma<HIDc, 1><<<grid, 256, SMEM_DYN>>>(b1, hseq1 + (size_t)t * HS, t);
    }
    tail_copy<<<(unsigned)((HS / 4 + 255) / 256), 256>>>(out);
}

// round 12
// speedup vs baseline: 1.8986x; 1.0160x over previous
#include <cuda_runtime.h>
#include <cuda_bf16.h>
#include <cstdint>

#define Hdim 64
#define Wdim 64
#define Bn   8
#define HIDc 32
#define Tn   16
#define CINx 16

#define PLANE 4224        // 66 rows x 64 bf16 per shifted plane

using u32 = unsigned int;
using u64 = unsigned long long;

// ---------------- persistent device scratch (no allocation) ----------------
__device__ float g_c0[(size_t)Bn * HIDc * 4096];
__device__ float g_c1[(size_t)Bn * HIDc * 4096];
// x input: [T*B*CIN][3 shifts][66][64] bf16, hi and lo planes.
__device__ __align__(128) __nv_bfloat16 g_xph[(size_t)Tn * Bn * CINx * 3 * PLANE];
__device__ __align__(128) __nv_bfloat16 g_xpl[(size_t)Tn * Bn * CINx * 3 * PLANE];
// hidden states: [parity][B*HID][3][66][64]
__device__ __align__(128) __nv_bfloat16 g_h0ph[2][(size_t)Bn * HIDc * 3 * PLANE];
__device__ __align__(128) __nv_bfloat16 g_h0pl[2][(size_t)Bn * HIDc * 3 * PLANE];
__device__ __align__(128) __nv_bfloat16 g_h1ph[2][(size_t)Bn * HIDc * 3 * PLANE];
__device__ __align__(128) __nv_bfloat16 g_h1pl[2][(size_t)Bn * HIDc * 3 * PLANE];
// weights [k][n] gate-interleaved, hi/lo
__device__ __align__(128) __nv_bfloat16 g_w0h[448 * 128], g_w0l[448 * 128];
__device__ __align__(128) __nv_bfloat16 g_w1h[576 * 128], g_w1l[576 * 128];

__device__ __forceinline__ float sigm(float v) {
    return __fdividef(1.0f, 1.0f + __expf(-v));
}
__device__ __forceinline__ float tanh_fast(float v) {
    return 2.0f * sigm(2.0f * v) - 1.0f;
}
__device__ __forceinline__ u32 smem_u32(const void* p) {
    u32 a;
    asm("{ .reg .u64 t; cvta.to.shared.u64 t, %1; cvt.u32.u64 %0, t; }"
        : "=r"(a) : "l"(p));
    return a;
}
__device__ __forceinline__ void ldsm4t(u32* r, u32 addr) {
    asm volatile("ldmatrix.sync.aligned.m8n8.x4.trans.shared.b16 {%0,%1,%2,%3}, [%4];"
                 : "=r"(r[0]), "=r"(r[1]), "=r"(r[2]), "=r"(r[3]) : "r"(addr));
}
__device__ __forceinline__ void mma16816(float* d, const u32* a, const u32* b) {
    asm volatile(
        "mma.sync.aligned.m16n8k16.row.col.f32.bf16.bf16.f32 "
        "{%0,%1,%2,%3}, {%4,%5,%6,%7}, {%8,%9}, {%0,%1,%2,%3};"
        : "+f"(d[0]), "+f"(d[1]), "+f"(d[2]), "+f"(d[3])
        : "r"(a[0]), "r"(a[1]), "r"(a[2]), "r"(a[3]), "r"(b[0]), "r"(b[1]));
}
__device__ __forceinline__ void cp16(u32 dst, const void* src) {
    asm volatile("cp.async.cg.shared.global [%0], [%1], 16;" :: "r"(dst), "l"(src));
}
#define CP_COMMIT() asm volatile("cp.async.commit_group;" ::: "memory")
#define CP_WAIT0()  asm volatile("cp.async.wait_group 0;" ::: "memory")

// ---------------- prepass kernels ----------------
// Build x shifted planes: plane[s] row (y+1) col c holds x[y][c+s-1] (0 OOB).
__global__ void build_x_planes(const float* __restrict__ x)
{
    size_t i = (size_t)blockIdx.x * blockDim.x + threadIdx.x;
    const size_t N = (size_t)Tn * Bn * CINx * 4096;
    if (i >= N) return;
    const size_t pi = i >> 12;           // (t*B+b)*CIN+ci
    const int px = (int)(i & 4095);
    const int y = px >> 6, xx = px & 63;
    const float v = x[i];
    const __nv_bfloat16 hh = __float2bfloat16(v);
    const __nv_bfloat16 hl = __float2bfloat16(v - __bfloat162float(hh));
    const size_t base = pi * 3 * PLANE + (size_t)(y + 1) * 64;
#pragma unroll
    for (int s = 0; s < 3; s++) {
        const int c = xx + 1 - s;
        if (c >= 0 && c < 64) {
            g_xph[base + (size_t)s * PLANE + c] = hh;
            g_xpl[base + (size_t)s * PLANE + c] = hl;
        }
    }
}

template<int LAYER>
__global__ void split_w_kernel(const float* __restrict__ Wt)
{
    constexpr int KLOG = (LAYER ? (HIDc + HIDc) : (CINx + HIDc)) * 9;   // 576 / 432
    constexpr int KPAD = LAYER ? 576 : 448;
    __nv_bfloat16* wh = LAYER ? g_w1h : g_w0h;
    __nv_bfloat16* wl = LAYER ? g_w1l : g_w0l;
    int idx = blockIdx.x * blockDim.x + threadIdx.x;
    if (idx < KPAD * 128) {
        int k = idx >> 7, n = idx & 127;
        int oc = (n & 3) * HIDc + (n >> 2);      // n = hc*4 + gate
        float v = (k < KLOG) ? Wt[(size_t)oc * KLOG + k] : 0.0f;
        __nv_bfloat16 h = __float2bfloat16(v);
        wh[idx] = h;
        wl[idx] = __float2bfloat16(v - __bfloat162float(h));
    }
}

// ---------------- main step kernel ----------------
#define RSTRB 272                 // bytes per smem k-row (128 elems *2B + 16B pad)
#define TILEU (32 * 68)           // u32 per tile (32 k-rows)
#define SMEM_DYN (2 * 4 * TILEU * 4)   // 2 buffers x 4 tiles = 69632 B

// Tile order within a buffer: [0]=A_hi [1]=A_lo [2]=B_hi [3]=B_lo
template<int CIN_X, int LAYER>
__global__ __launch_bounds__(256, 2)
void step_mma(const float* __restrict__ bias,
              float* __restrict__ h_out,     // fp32 h_seq slab for this t
              int t)
{
    constexpr int CIN_TOT = CIN_X + HIDc;
    constexpr int KLOG = CIN_TOT * 9;
    constexpr int NCH  = (KLOG + 31) / 32;    // 14 / 18

    extern __shared__ __align__(128) u32 dsm[];
    __shared__ float sb[128];

    const int tid = threadIdx.x;
    const int l = tid & 31;
    const int w = tid >> 5;
    const int b = blockIdx.y;
    const int y0 = blockIdx.x * 2;
    const int t0 = (t == 0);
    float* c_state = LAYER ? g_c1 : g_c0;
    __nv_bfloat16* hph = LAYER ? g_h1ph[t & 1] : g_h0ph[t & 1];
    __nv_bfloat16* hpl = LAYER ? g_h1pl[t & 1] : g_h0pl[t & 1];

    if (tid < 128) {
        const int hc = tid >> 2, g = tid & 3;
        sb[tid] = bias[g * HIDc + hc];
    }

    // warp tile: wm in {0,32,64,96}, wn in {0,64}
    const int wm = (w & 3) * 32;
    const int wn = (w >> 2) * 64;

    const u32 smb = smem_u32(dsm);
    // ldmatrix lane base offsets (bytes) — validated in R9/R10/R11
    const u32 aLane = (u32)(((l & 7) + ((l >> 4) & 1) * 8) * RSTRB + ((l >> 3) & 1) * 16);
    const u32 bLane = (u32)(((l & 7) + ((l >> 3) & 1) * 8) * RSTRB + ((l >> 4) & 1) * 16);

    float acc[2][8][4];
#pragma unroll
    for (int mi = 0; mi < 2; mi++)
#pragma unroll
        for (int ni = 0; ni < 8; ni++)
#pragma unroll
            for (int q = 0; q < 4; q++) acc[mi][ni][q] = 0.0f;

    // ---------------- staging: pure cp.async, 8 x 16B per thread ----------------
    auto stage = [&](int ch, int buf) {
        const int kr  = tid >> 3;            // 0..31
        const int sub = tid & 7;             // 0..7
        const int k = ch * 32 + kr;
        int ci = k / 9;
        const int rem = k - ci * 9;
        const int ky = rem / 3;              // 0..2 (offset = ky-1)
        int s = rem - ky * 3;                // kx+1
        bool zero = (k >= KLOG);
        if (zero) { ci = 0; s = 0; }
        const __nv_bfloat16 *ph, *pl;
        if (LAYER == 0) {
            if (ci < CIN_X) {
                const size_t pi = ((size_t)((t * Bn + b) * CINx + ci) * 3 + s) * PLANE;
                ph = g_xph + pi; pl = g_xpl + pi;
            } else {
                if (t0) zero = true;
                const size_t pi = ((size_t)(b * HIDc + (ci - CIN_X)) * 3 + s) * PLANE;
                ph = g_h0ph[(t + 1) & 1] + pi; pl = g_h0pl[(t + 1) & 1] + pi;
            }
        } else {
            if (ci < HIDc) {
                const size_t pi = ((size_t)(b * HIDc + ci) * 3 + s) * PLANE;
                ph = g_h0ph[t & 1] + pi; pl = g_h0pl[t & 1] + pi;
            } else {
                if (t0) zero = true;
                const size_t pi = ((size_t)(b * HIDc + (ci - HIDc)) * 3 + s) * PLANE;
                ph = g_h1ph[(t + 1) & 1] + pi; pl = g_h1pl[(t + 1) & 1] + pi;
            }
        }
#pragma unroll
        for (int j = 0; j < 4; j++) {
            const int op = sub * 4 + j;      // 0..31
            const int tsel = op >> 4;        // 0 = hi tile, 1 = lo tile
            const int seg = op & 15;         // 16B segment within k-row
            const int prow = zero ? 0 : (y0 + ky + (seg >> 3));  // plane row
            const __nv_bfloat16* src = (tsel ? pl : ph) + prow * 64 + (seg & 7) * 8;
            const u32 dst = smb + (u32)(((buf * 4 + tsel) * TILEU + kr * 68) * 4)
                                + (u32)(seg * 16);
            cp16(dst, src);
        }
        // B: both planes; 32 rows x 16 segs per tile
        const __nv_bfloat16* wph = LAYER ? g_w1h : g_w0h;
        const __nv_bfloat16* wpl = LAYER ? g_w1l : g_w0l;
        const u32 Bh = smb + (u32)((buf * 4 + 2) * TILEU) * 4u;
        const u32 Bl = smb + (u32)((buf * 4 + 3) * TILEU) * 4u;
#pragma unroll
        for (int it = 0; it < 2; it++) {
            const int idx = tid + it * 256;
            const int row = idx >> 4;
            const int seg = idx & 15;
            const u32 dof = (u32)(row * 68 + seg * 4) * 4u;
            const size_t sof = (size_t)(ch * 32 + row) * 128 + seg * 8;
            cp16(Bh + dof, wph + sof);
            cp16(Bl + dof, wpl + sof);
        }
        CP_COMMIT();
    };

    // ---------------- compute: fragment-reuse split passes ----------------
    // Per k16: load Ah, Al, Bh once -> 32 MMAs; reload B regs from Bl -> 16 MMAs.
    auto compute = [&](int buf) {
        const u32 Ah = smb + (u32)((buf * 4 + 0) * TILEU) * 4u;
        const u32 Al = smb + (u32)((buf * 4 + 1) * TILEU) * 4u;
        const u32 Bh = smb + (u32)((buf * 4 + 2) * TILEU) * 4u;
        const u32 Bl = smb + (u32)((buf * 4 + 3) * TILEU) * 4u;
#pragma unroll
        for (int k16 = 0; k16 < 2; k16++) {
            const u32 kofs = (u32)(k16 * 16 * RSTRB);
            u32 ah0[4], ah1[4], al0[4], al1[4];
            ldsm4t(ah0, Ah + kofs + aLane + (u32)(wm * 2));
            ldsm4t(ah1, Ah + kofs + aLane + (u32)((wm + 16) * 2));
            ldsm4t(al0, Al + kofs + aLane + (u32)(wm * 2));
            ldsm4t(al1, Al + kofs + aLane + (u32)((wm + 16) * 2));
            u32 bb[16];
#pragma unroll
            for (int q = 0; q < 4; q++)
                ldsm4t(bb + q * 4, Bh + kofs + bLane + (u32)((wn + q * 16) * 2));
            // pass 0: Ah x Bh
#pragma unroll
            for (int ni = 0; ni < 8; ni++) {
                const u32* bf = &bb[(ni >> 1) * 4 + (ni & 1) * 2];
                mma16816(acc[0][ni], ah0, bf);
                mma16816(acc[1][ni], ah1, bf);
            }
            // pass 1: Al x Bh (same B fragments)
#pragma unroll
            for (int ni = 0; ni < 8; ni++) {
                const u32* bf = &bb[(ni >> 1) * 4 + (ni & 1) * 2];
                mma16816(acc[0][ni], al0, bf);
                mma16816(acc[1][ni], al1, bf);
            }
            // reload B registers from Bl tile
#pragma unroll
            for (int q = 0; q < 4; q++)
                ldsm4t(bb + q * 4, Bl + kofs + bLane + (u32)((wn + q * 16) * 2));
            // pass 2: Ah x Bl (reused A fragments)
#pragma unroll
            for (int ni = 0; ni < 8; ni++) {
                const u32* bf = &bb[(ni >> 1) * 4 + (ni & 1) * 2];
                mma16816(acc[0][ni], ah0, bf);
                mma16816(acc[1][ni], ah1, bf);
            }
        }
    };

    // ---------------- pipelined chunk loop ----------------
    stage(0, 0);
    for (int c = 0; c < NCH; c++) {
        CP_WAIT0();
        __syncthreads();
        if (c + 1 < NCH) stage(c + 1, (c + 1) & 1);
        compute(c & 1);
    }

    // ---------------- epilogue: gate math + h plane writes ----------------
    const int tig = l & 3;
    const int rr = l >> 2;
#pragma unroll
    for (int mi = 0; mi < 2; mi++) {
#pragma unroll
        for (int ni = 0; ni < 8; ni++) {
            float* d = acc[mi][ni];
            const float s0 = (tig & 1) ? d[0] : d[2];
            const float s1 = (tig & 1) ? d[1] : d[3];
            const float r0 = __shfl_xor_sync(0xffffffffu, s0, 1);
            const float r1 = __shfl_xor_sync(0xffffffffu, s1, 1);
            float iv, fv, ov, gv;
            int px;
            if (tig & 1) { iv = r0; fv = r1; ov = d[2]; gv = d[3]; px = wm + mi * 16 + rr + 8; }
            else         { iv = d[0]; fv = d[1]; ov = r0; gv = r1; px = wm + mi * 16 + rr; }
            const int hc = ((wn + ni * 8) >> 2) + (tig >> 1);
            iv += sb[hc * 4 + 0];
            fv += sb[hc * 4 + 1];
            ov += sb[hc * 4 + 2];
            gv += sb[hc * 4 + 3];
            const int yy = y0 + (px >> 6);
            const int xx = px & 63;
            const size_t off = (((size_t)b * HIDc + hc) * Hdim + yy) * Wdim + xx;
            const float cp = t0 ? 0.0f : c_state[off];
            const float cn = sigm(fv) * cp + sigm(iv) * tanh_fast(gv);
            const float hn = sigm(ov) * tanh_fast(cn);
            c_state[off] = cn;
            h_out[off] = hn;
            const __nv_bfloat16 hh = __float2bfloat16(hn);
            const __nv_bfloat16 hl = __float2bfloat16(hn - __bfloat162float(hh));
            const size_t pb = (size_t)(b * HIDc + hc) * 3 * PLANE + (size_t)(yy + 1) * 64;
#pragma unroll
            for (int s2 = 0; s2 < 3; s2++) {
                const int cc = xx + 1 - s2;
                if (cc >= 0 && cc < 64) {
                    hph[pb + (size_t)s2 * PLANE + cc] = hh;
                    hpl[pb + (size_t)s2 * PLANE + cc] = hl;
                }
            }
        }
    }
}

// Writes the four tail regions: h0_T, c0_T, h1_T, c1_T.
__global__ void tail_copy(float* __restrict__ out)
{
    const size_t NP = (size_t)Bn * HIDc * 4096;
    size_t i4 = (size_t)blockIdx.x * blockDim.x + threadIdx.x;
    const size_t N4 = NP / 4;
    if (i4 < N4) {
        const size_t SEQ = Tn * NP;
        float4* o4 = (float4*)out;
        const float4* c0 = (const float4*)g_c0;
        const float4* c1 = (const float4*)g_c1;
        const size_t base = (2 * SEQ) / 4;
        o4[base + 0 * N4 + i4] = o4[((Tn - 1) * NP) / 4 + i4];
        o4[base + 1 * N4 + i4] = c0[i4];
        o4[base + 2 * N4 + i4] = o4[(SEQ + (Tn - 1) * NP) / 4 + i4];
        o4[base + 3 * N4 + i4] = c1[i4];
    }
}

extern "C" void kernel_launch(void* const* d_in, const int* in_sizes, int n_in,
                              void* d_out, int out_size)
{
    const float* x  = (const float*)d_in[0];
    const float* W0 = (const float*)d_in[1];
    const float* b0 = (const float*)d_in[2];
    const float* W1 = (const float*)d_in[3];
    const float* b1 = (const float*)d_in[4];
    float* out = (float*)d_out;

    cudaFuncSetAttribute(step_mma<CINx, 0>,
                         cudaFuncAttributeMaxDynamicSharedMemorySize, SMEM_DYN);
    cudaFuncSetAttribute(step_mma<HIDc, 1>,
                         cudaFuncAttributeMaxDynamicSharedMemorySize, SMEM_DYN);

    const size_t HS = (size_t)Bn * HIDc * 4096;
    float* hseq0 = out;
    float* hseq1 = out + (size_t)Tn * HS;

    // prepasses (deterministic each replay)
    {
        const size_t NX = (size_t)Tn * Bn * CINx * 4096;
        build_x_planes<<<(unsigned)((NX + 255) / 256), 256>>>(x);
        split_w_kernel<0><<<(448 * 128 + 255) / 256, 256>>>(W0);
        split_w_kernel<1><<<(576 * 128 + 255) / 256, 256>>>(W1);
    }

    dim3 grid(32, Bn);
    for (int t = 0; t < Tn; t++) {
        step_mma<CINx, 0><<<grid, 256, SMEM_DYN>>>(b0, hseq0 + (size_t)t * HS, t);
        step_mma<HIDc, 1><<<grid, 256, SMEM_DYN>>>(b1, hseq1 + (size_t)t * HS, t);
    }
    tail_copy<<<(unsigned)((HS / 4 + 255) / 256), 256>>>(out);
}

// round 13
// speedup vs baseline: 2.3409x; 1.2330x over previous
#include <cuda_runtime.h>
#include <cuda_bf16.h>
#include <cstdint>

#define Hdim 64
#define Wdim 64
#define Bn   8
#define HIDc 32
#define Tn   16
#define CINx 16

#define PLANE 4224        // 66 rows x 64 bf16 per shifted plane

using u32 = unsigned int;
using u64 = unsigned long long;

// ---------------- persistent device scratch (no allocation) ----------------
__device__ float g_c0[(size_t)Bn * HIDc * 4096];
__device__ float g_c1[(size_t)Bn * HIDc * 4096];
// x input: [T*B*CIN][3 shifts][66][64] bf16, hi and lo planes.
__device__ __align__(128) __nv_bfloat16 g_xph[(size_t)Tn * Bn * CINx * 3 * PLANE];
__device__ __align__(128) __nv_bfloat16 g_xpl[(size_t)Tn * Bn * CINx * 3 * PLANE];
// hidden states: [parity][B*HID][3][66][64]
__device__ __align__(128) __nv_bfloat16 g_h0ph[2][(size_t)Bn * HIDc * 3 * PLANE];
__device__ __align__(128) __nv_bfloat16 g_h0pl[2][(size_t)Bn * HIDc * 3 * PLANE];
__device__ __align__(128) __nv_bfloat16 g_h1ph[2][(size_t)Bn * HIDc * 3 * PLANE];
__device__ __align__(128) __nv_bfloat16 g_h1pl[2][(size_t)Bn * HIDc * 3 * PLANE];
// weights [k][n] gate-interleaved, hi/lo
__device__ __align__(128) __nv_bfloat16 g_w0h[448 * 128], g_w0l[448 * 128];
__device__ __align__(128) __nv_bfloat16 g_w1h[576 * 128], g_w1l[576 * 128];
// permanently-zero 256B source for padded/t0 rows (device globals are zero-init;
// the plane halo rows already rely on this).
__device__ __align__(128) __nv_bfloat16 g_zero[128];

__device__ __forceinline__ float sigm(float v) {
    return __fdividef(1.0f, 1.0f + __expf(-v));
}
__device__ __forceinline__ float tanh_fast(float v) {
    return 2.0f * sigm(2.0f * v) - 1.0f;
}
__device__ __forceinline__ u32 smem_u32(const void* p) {
    u32 a;
    asm("{ .reg .u64 t; cvta.to.shared.u64 t, %1; cvt.u32.u64 %0, t; }"
        : "=r"(a) : "l"(p));
    return a;
}
__device__ __forceinline__ void ldsm4t(u32* r, u32 addr) {
    asm volatile("ldmatrix.sync.aligned.m8n8.x4.trans.shared.b16 {%0,%1,%2,%3}, [%4];"
                 : "=r"(r[0]), "=r"(r[1]), "=r"(r[2]), "=r"(r[3]) : "r"(addr));
}
__device__ __forceinline__ void mma16816(float* d, const u32* a, const u32* b) {
    asm volatile(
        "mma.sync.aligned.m16n8k16.row.col.f32.bf16.bf16.f32 "
        "{%0,%1,%2,%3}, {%4,%5,%6,%7}, {%8,%9}, {%0,%1,%2,%3};"
        : "+f"(d[0]), "+f"(d[1]), "+f"(d[2]), "+f"(d[3])
        : "r"(a[0]), "r"(a[1]), "r"(a[2]), "r"(a[3]), "r"(b[0]), "r"(b[1]));
}
// 256B bulk copy global->shared, completion counted on mbarrier.
__device__ __forceinline__ void bulk256(u32 dst, const void* src, u32 mbar) {
    asm volatile(
        "cp.async.bulk.shared::cta.global.mbarrier::complete_tx::bytes [%0], [%1], 256, [%2];"
        :: "r"(dst), "l"(src), "r"(mbar) : "memory");
}
__device__ __forceinline__ void mbar_arrive_tx256(u32 mbar) {
    asm volatile("mbarrier.arrive.expect_tx.shared::cta.b64 _, [%0], 256;"
                 :: "r"(mbar) : "memory");
}
__device__ __forceinline__ void mbar_wait(u32 addr, u32 parity) {
    asm volatile(
        "{\n\t.reg .pred P;\n\t"
        "W%=:\n\t"
        "mbarrier.try_wait.parity.acquire.cta.shared::cta.b64 P, [%0], %1, 0x989680;\n\t"
        "@!P bra W%=;\n\t}"
        :: "r"(addr), "r"(parity) : "memory");
}

// ---------------- prepass kernels ----------------
// Build x shifted planes: plane[s] row (y+1) col c holds x[y][c+s-1] (0 OOB).
__global__ void build_x_planes(const float* __restrict__ x)
{
    size_t i = (size_t)blockIdx.x * blockDim.x + threadIdx.x;
    const size_t N = (size_t)Tn * Bn * CINx * 4096;
    if (i >= N) return;
    const size_t pi = i >> 12;           // (t*B+b)*CIN+ci
    const int px = (int)(i & 4095);
    const int y = px >> 6, xx = px & 63;
    const float v = x[i];
    const __nv_bfloat16 hh = __float2bfloat16(v);
    const __nv_bfloat16 hl = __float2bfloat16(v - __bfloat162float(hh));
    const size_t base = pi * 3 * PLANE + (size_t)(y + 1) * 64;
#pragma unroll
    for (int s = 0; s < 3; s++) {
        const int c = xx + 1 - s;
        if (c >= 0 && c < 64) {
            g_xph[base + (size_t)s * PLANE + c] = hh;
            g_xpl[base + (size_t)s * PLANE + c] = hl;
        }
    }
}

template<int LAYER>
__global__ void split_w_kernel(const float* __restrict__ Wt)
{
    constexpr int KLOG = (LAYER ? (HIDc + HIDc) : (CINx + HIDc)) * 9;   // 576 / 432
    constexpr int KPAD = LAYER ? 576 : 448;
    __nv_bfloat16* wh = LAYER ? g_w1h : g_w0h;
    __nv_bfloat16* wl = LAYER ? g_w1l : g_w0l;
    int idx = blockIdx.x * blockDim.x + threadIdx.x;
    if (idx < KPAD * 128) {
        int k = idx >> 7, n = idx & 127;
        int oc = (n & 3) * HIDc + (n >> 2);      // n = hc*4 + gate
        float v = (k < KLOG) ? Wt[(size_t)oc * KLOG + k] : 0.0f;
        __nv_bfloat16 h = __float2bfloat16(v);
        wh[idx] = h;
        wl[idx] = __float2bfloat16(v - __bfloat162float(h));
    }
}

// ---------------- main step kernel ----------------
#define RSTRB 272                 // bytes per smem k-row (128 elems *2B + 16B pad)
#define TILEU (32 * 68)           // u32 per tile (32 k-rows)
#define SMEM_DYN (2 * 4 * TILEU * 4)   // 2 buffers x 4 tiles = 69632 B

// Tile order within a buffer: [0]=A_hi [1]=A_lo [2]=B_hi [3]=B_lo
template<int CIN_X, int LAYER>
__global__ __launch_bounds__(256, 2)
void step_mma(const float* __restrict__ bias,
              float* __restrict__ h_out,     // fp32 h_seq slab for this t
              int t)
{
    constexpr int CIN_TOT = CIN_X + HIDc;
    constexpr int KLOG = CIN_TOT * 9;
    constexpr int NCH  = (KLOG + 31) / 32;    // 14 / 18

    extern __shared__ __align__(128) u32 dsm[];
    __shared__ float sb[128];
    __shared__ __align__(8) u64 s_mbar[2];

    const int tid = threadIdx.x;
    const int l = tid & 31;
    const int w = tid >> 5;
    const int b = blockIdx.y;
    const int y0 = blockIdx.x * 2;
    const int t0 = (t == 0);
    float* c_state = LAYER ? g_c1 : g_c0;
    __nv_bfloat16* hph = LAYER ? g_h1ph[t & 1] : g_h0ph[t & 1];
    __nv_bfloat16* hpl = LAYER ? g_h1pl[t & 1] : g_h0pl[t & 1];

    if (tid < 128) {
        const int hc = tid >> 2, g = tid & 3;
        sb[tid] = bias[g * HIDc + hc];
    }
    const u32 mb0 = smem_u32(&s_mbar[0]);
    const u32 mb1 = smem_u32(&s_mbar[1]);
    if (tid == 0) {
        asm volatile("mbarrier.init.shared.b64 [%0], 128;" :: "r"(mb0) : "memory");
        asm volatile("mbarrier.init.shared.b64 [%0], 128;" :: "r"(mb1) : "memory");
    }
    __syncthreads();

    // warp tile: wm in {0,32,64,96}, wn in {0,64}
    const int wm = (w & 3) * 32;
    const int wn = (w >> 2) * 64;

    const u32 smb = smem_u32(dsm);
    // ldmatrix lane base offsets (bytes) — validated since R9
    const u32 aLane = (u32)(((l & 7) + ((l >> 4) & 1) * 8) * RSTRB + ((l >> 3) & 1) * 16);
    const u32 bLane = (u32)(((l & 7) + ((l >> 3) & 1) * 8) * RSTRB + ((l >> 4) & 1) * 16);

    float acc[2][8][4];
#pragma unroll
    for (int mi = 0; mi < 2; mi++)
#pragma unroll
        for (int ni = 0; ni < 8; ni++)
#pragma unroll
            for (int q = 0; q < 4; q++) acc[mi][ni][q] = 0.0f;

    // ---------------- staging: 128 x 256B bulk copies per chunk ----------------
    // tid 0..63  : A rows  (tsel = hi/lo, kr = k-row)
    // tid 64..127: B rows
    auto stage = [&](int ch, int buf) {
        if (tid >= 128) return;
        const u32 mb = buf ? mb1 : mb0;
        const int grp  = tid >> 6;          // 0 = A, 1 = B
        const int tsel = (tid >> 5) & 1;    // 0 = hi, 1 = lo
        const int kr   = tid & 31;
        const __nv_bfloat16* src;
        if (grp == 0) {
            const int k = ch * 32 + kr;
            int ci = k / 9;
            const int rem = k - ci * 9;
            const int ky = rem / 3;          // 0..2
            int s = rem - ky * 3;            // kx+1
            bool zero = (k >= KLOG);
            if (zero) { ci = 0; s = 0; }
            const __nv_bfloat16* plane;
            if (LAYER == 0) {
                if (ci < CIN_X) {
                    const size_t pi = ((size_t)((t * Bn + b) * CINx + ci) * 3 + s) * PLANE;
                    plane = (tsel ? g_xpl : g_xph) + pi;
                } else {
                    if (t0) zero = true;
                    const size_t pi = ((size_t)(b * HIDc + (ci - CIN_X)) * 3 + s) * PLANE;
                    plane = (tsel ? g_h0pl[(t + 1) & 1] : g_h0ph[(t + 1) & 1]) + pi;
                }
            } else {
                if (ci < HIDc) {
                    const size_t pi = ((size_t)(b * HIDc + ci) * 3 + s) * PLANE;
                    plane = (tsel ? g_h0pl[t & 1] : g_h0ph[t & 1]) + pi;
                } else {
                    if (t0) zero = true;
                    const size_t pi = ((size_t)(b * HIDc + (ci - HIDc)) * 3 + s) * PLANE;
                    plane = (tsel ? g_h1pl[(t + 1) & 1] : g_h1ph[(t + 1) & 1]) + pi;
                }
            }
            src = zero ? g_zero : (plane + (size_t)(y0 + ky) * 64);
        } else {
            const __nv_bfloat16* wp = LAYER ? (tsel ? g_w1l : g_w1h)
                                            : (tsel ? g_w0l : g_w0h);
            src = wp + (size_t)(ch * 32 + kr) * 128;
        }
        const int tile = buf * 4 + grp * 2 + tsel;
        const u32 dst = smb + (u32)(tile * TILEU + kr * 68) * 4u;
        mbar_arrive_tx256(mb);
        bulk256(dst, src, mb);
    };

    // ---------------- compute: fragment-reuse split passes (validated R12) ----
    auto compute = [&](int buf) {
        const u32 Ah = smb + (u32)((buf * 4 + 0) * TILEU) * 4u;
        const u32 Al = smb + (u32)((buf * 4 + 1) * TILEU) * 4u;
        const u32 Bh = smb + (u32)((buf * 4 + 2) * TILEU) * 4u;
        const u32 Bl = smb + (u32)((buf * 4 + 3) * TILEU) * 4u;
#pragma unroll
        for (int k16 = 0; k16 < 2; k16++) {
            const u32 kofs = (u32)(k16 * 16 * RSTRB);
            u32 ah0[4], ah1[4], al0[4], al1[4];
            ldsm4t(ah0, Ah + kofs + aLane + (u32)(wm * 2));
            ldsm4t(ah1, Ah + kofs + aLane + (u32)((wm + 16) * 2));
            ldsm4t(al0, Al + kofs + aLane + (u32)(wm * 2));
            ldsm4t(al1, Al + kofs + aLane + (u32)((wm + 16) * 2));
            u32 bb[16];
#pragma unroll
            for (int q = 0; q < 4; q++)
                ldsm4t(bb + q * 4, Bh + kofs + bLane + (u32)((wn + q * 16) * 2));
#pragma unroll
            for (int ni = 0; ni < 8; ni++) {
                const u32* bf = &bb[(ni >> 1) * 4 + (ni & 1) * 2];
                mma16816(acc[0][ni], ah0, bf);
                mma16816(acc[1][ni], ah1, bf);
            }
#pragma unroll
            for (int ni = 0; ni < 8; ni++) {
                const u32* bf = &bb[(ni >> 1) * 4 + (ni & 1) * 2];
                mma16816(acc[0][ni], al0, bf);
                mma16816(acc[1][ni], al1, bf);
            }
#pragma unroll
            for (int q = 0; q < 4; q++)
                ldsm4t(bb + q * 4, Bl + kofs + bLane + (u32)((wn + q * 16) * 2));
#pragma unroll
            for (int ni = 0; ni < 8; ni++) {
                const u32* bf = &bb[(ni >> 1) * 4 + (ni & 1) * 2];
                mma16816(acc[0][ni], ah0, bf);
                mma16816(acc[1][ni], ah1, bf);
            }
        }
    };

    // ---------------- pipelined chunk loop ----------------
    int ph0 = 0, ph1 = 0;
    stage(0, 0);
    for (int c = 0; c < NCH; c++) {
        __syncthreads();                       // all warps done with buf (c+1)&1
        if (c + 1 < NCH) stage(c + 1, (c + 1) & 1);
        if ((c & 1) == 0) { mbar_wait(mb0, ph0); ph0 ^= 1; }
        else              { mbar_wait(mb1, ph1); ph1 ^= 1; }
        compute(c & 1);
    }

    // ---------------- epilogue: gate math + h plane writes (validated) -------
    const int tig = l & 3;
    const int rr = l >> 2;
#pragma unroll
    for (int mi = 0; mi < 2; mi++) {
#pragma unroll
        for (int ni = 0; ni < 8; ni++) {
            float* d = acc[mi][ni];
            const float s0 = (tig & 1) ? d[0] : d[2];
            const float s1 = (tig & 1) ? d[1] : d[3];
            const float r0 = __shfl_xor_sync(0xffffffffu, s0, 1);
            const float r1 = __shfl_xor_sync(0xffffffffu, s1, 1);
            float iv, fv, ov, gv;
            int px;
            if (tig & 1) { iv = r0; fv = r1; ov = d[2]; gv = d[3]; px = wm + mi * 16 + rr + 8; }
            else         { iv = d[0]; fv = d[1]; ov = r0; gv = r1; px = wm + mi * 16 + rr; }
            const int hc = ((wn + ni * 8) >> 2) + (tig >> 1);
            iv += sb[hc * 4 + 0];
            fv += sb[hc * 4 + 1];
            ov += sb[hc * 4 + 2];
            gv += sb[hc * 4 + 3];
            const int yy = y0 + (px >> 6);
            const int xx = px & 63;
            const size_t off = (((size_t)b * HIDc + hc) * Hdim + yy) * Wdim + xx;
            const float cp = t0 ? 0.0f : c_state[off];
            const float cn = sigm(fv) * cp + sigm(iv) * tanh_fast(gv);
            const float hn = sigm(ov) * tanh_fast(cn);
            c_state[off] = cn;
            h_out[off] = hn;
            const __nv_bfloat16 hh = __float2bfloat16(hn);
            const __nv_bfloat16 hl = __float2bfloat16(hn - __bfloat162float(hh));
            const size_t pb = (size_t)(b * HIDc + hc) * 3 * PLANE + (size_t)(yy + 1) * 64;
#pragma unroll
            for (int s2 = 0; s2 < 3; s2++) {
                const int cc = xx + 1 - s2;
                if (cc >= 0 && cc < 64) {
                    hph[pb + (size_t)s2 * PLANE + cc] = hh;
                    hpl[pb + (size_t)s2 * PLANE + cc] = hl;
                }
            }
        }
    }
}

// Writes the four tail regions: h0_T, c0_T, h1_T, c1_T.
__global__ void tail_copy(float* __restrict__ out)
{
    const size_t NP = (size_t)Bn * HIDc * 4096;
    size_t i4 = (size_t)blockIdx.x * blockDim.x + threadIdx.x;
    const size_t N4 = NP / 4;
    if (i4 < N4) {
        const size_t SEQ = Tn * NP;
        float4* o4 = (float4*)out;
        const float4* c0 = (const float4*)g_c0;
        const float4* c1 = (const float4*)g_c1;
        const size_t base = (2 * SEQ) / 4;
        o4[base + 0 * N4 + i4] = o4[((Tn - 1) * NP) / 4 + i4];
        o4[base + 1 * N4 + i4] = c0[i4];
        o4[base + 2 * N4 + i4] = o4[(SEQ + (Tn - 1) * NP) / 4 + i4];
        o4[base + 3 * N4 + i4] = c1[i4];
    }
}

extern "C" void kernel_launch(void* const* d_in, const int* in_sizes, int n_in,
                              void* d_out, int out_size)
{
    const float* x  = (const float*)d_in[0];
    const float* W0 = (const float*)d_in[1];
    const float* b0 = (const float*)d_in[2];
    const float* W1 = (const float*)d_in[3];
    const float* b1 = (const float*)d_in[4];
    float* out = (float*)d_out;

    cudaFuncSetAttribute(step_mma<CINx, 0>,
                         cudaFuncAttributeMaxDynamicSharedMemorySize, SMEM_DYN);
    cudaFuncSetAttribute(step_mma<HIDc, 1>,
                         cudaFuncAttributeMaxDynamicSharedMemorySize, SMEM_DYN);

    const size_t HS = (size_t)Bn * HIDc * 4096;
    float* hseq0 = out;
    float* hseq1 = out + (size_t)Tn * HS;

    // prepasses (deterministic each replay)
    {
        const size_t NX = (size_t)Tn * Bn * CINx * 4096;
        build_x_planes<<<(unsigned)((NX + 255) / 256), 256>>>(x);
        split_w_kernel<0><<<(448 * 128 + 255) / 256, 256>>>(W0);
        split_w_kernel<1><<<(576 * 128 + 255) / 256, 256>>>(W1);
    }

    dim3 grid(32, Bn);
    for (int t = 0; t < Tn; t++) {
        step_mma<CINx, 0><<<grid, 256, SMEM_DYN>>>(b0, hseq0 + (size_t)t * HS, t);
        step_mma<HIDc, 1><<<grid, 256, SMEM_DYN>>>(b1, hseq1 + (size_t)t * HS, t);
    }
    tail_copy<<<(unsigned)((HS / 4 + 255) / 256), 256>>>(out);
}